// round 2
// baseline (speedup 1.0000x reference)
#include <cuda_runtime.h>
#include <cuda_fp16.h>

// Harness upcasts jnp.float16 arrays to float32 (float16 absent from the
// supported-dtype table). So:
//   x:      [N=16384, DIM=4096] f32 (f16-valued)
//   pairs:  [KROT=8, DIM]       int32 (same local pattern tiled per 128-group)
//   theta:  [KROT, DIM/2]       f32 (f16-valued)
//   scales: [1, DIM]            f32 (f16-valued)
//   out:    [N, DIM]            f32
// Internally we replicate the reference's fp16 per-op rounding exactly.
#define DIMV   4096
#define KROT   8
#define NPAIR  2048      // DIM/2 pairs per layer
#define GRP    128
#define NGRP   32        // DIM/GRP
#define ILG    64        // pairs per group per layer
#define ROWS   4         // rows per block (2 half2 planes)

// Scratch (static device globals — no allocation).
// g_cs layout: [k][il*32 + g]  -> warp (lanes = g) reads one coalesced 128B line.
__device__ __half2  g_cs[KROT * NPAIR];
__device__ unsigned g_ab[KROT * ILG];

// XOR swizzle: conflict-free when lanes vary g at fixed channel c.
__device__ __forceinline__ int swz(int c, int g) {
    return c * NGRP + (g ^ (c & 31));
}

__global__ void prep_kernel(const float* __restrict__ theta,
                            const int* __restrict__ pairs) {
    int idx = blockIdx.x * blockDim.x + threadIdx.x;
    if (idx < KROT * NPAIR) {
        int k  = idx >> 11;          // / 2048
        int i  = idx & (NPAIR - 1);  // pair index within layer
        int g  = i >> 6;             // group
        int il = i & (ILG - 1);      // local pair within group
        float t = theta[idx];        // f16-valued f32; cos/sin in f32 like reference
        __half c = __float2half(cosf(t));
        __half s = __float2half(sinf(t));
        g_cs[(k << 11) + il * NGRP + g] = __halves2half2(c, s);
    }
    if (idx < KROT * ILG) {
        int k  = idx >> 6;
        int il = idx & (ILG - 1);
        int a = pairs[k * DIMV + 2 * il];       // local indices (0..127), same for all groups
        int b = pairs[k * DIMV + 2 * il + 1];
        g_ab[idx] = (unsigned)(a | (b << 8));
    }
}

__global__ void __launch_bounds__(256)
rot_kernel(const float* __restrict__ x,
           const float* __restrict__ scales,
           float* __restrict__ out) {
    // Channel-major tiles, 2 rows packed per half2. 32KB total.
    __shared__ __half2 sA[GRP * NGRP];   // rows r0, r0+1
    __shared__ __half2 sB[GRP * NGRP];   // rows r0+2, r0+3

    const int tid = threadIdx.x;
    const size_t base = (size_t)blockIdx.x * ROWS * DIMV;

    // ---- Load: global f32 (row-major, coalesced float2) -> shared half (channel-major) ----
    #pragma unroll
    for (int m = 0; m < 8; m++) {
        int d0 = (tid + m * 256) * 2;        // channel pair (d0, d0+1)
        int c = d0 & (GRP - 1), g = d0 >> 7;
        float2 v0 = *(const float2*)(x + base + d0);
        float2 v1 = *(const float2*)(x + base + DIMV + d0);
        float2 v2 = *(const float2*)(x + base + 2 * DIMV + d0);
        float2 v3 = *(const float2*)(x + base + 3 * DIMV + d0);
        int w0 = swz(c, g), w1 = swz(c + 1, g);
        sA[w0] = __floats2half2_rn(v0.x, v1.x);   // (row0, row1) @ channel d0
        sA[w1] = __floats2half2_rn(v0.y, v1.y);   // (row0, row1) @ channel d0+1
        sB[w0] = __floats2half2_rn(v2.x, v3.x);
        sB[w1] = __floats2half2_rn(v2.y, v3.y);
    }
    __syncthreads();

    // ---- Rotation: warp lanes = 32 groups (conflict-free), warp = 8 local pairs ----
    const int g = tid & 31;
    const int ilbase = (tid >> 5) * 8;

    #pragma unroll
    for (int k = 0; k < KROT; k++) {
        #pragma unroll
        for (int m = 0; m < 8; m++) {
            int il = ilbase + m;
            unsigned ab = g_ab[(k << 6) + il];            // warp-uniform broadcast
            int a = ab & 255, b = ab >> 8;
            __half2 cs = g_cs[(k << 11) + il * NGRP + g]; // coalesced 128B line
            __half2 hc = __half2half2(__low2half(cs));
            __half2 hs = __half2half2(__high2half(cs));
            int wa = swz(a, g), wb = swz(b, g);
            __half2 xa0 = sA[wa], xb0 = sA[wb];
            __half2 xa1 = sB[wa], xb1 = sB[wb];
            // Exact reference arithmetic: per-op f16 rounding, same order.
            sA[wa] = __hsub2(__hmul2(hc, xa0), __hmul2(hs, xb0));
            sA[wb] = __hadd2(__hmul2(hs, xa0), __hmul2(hc, xb0));
            sB[wa] = __hsub2(__hmul2(hc, xa1), __hmul2(hs, xb1));
            sB[wb] = __hadd2(__hmul2(hs, xa1), __hmul2(hc, xb1));
        }
        __syncthreads();   // pairs disjoint within a layer; sync only between layers
    }

    // ---- Store: shared half (channel-major) -> global f32 (row-major) with f16 scaling ----
    #pragma unroll
    for (int m = 0; m < 8; m++) {
        int d0 = (tid + m * 256) * 2;
        int c = d0 & (GRP - 1), gg = d0 >> 7;
        int w0 = swz(c, gg), w1 = swz(c + 1, gg);
        __half2 A0 = sA[w0], A1 = sA[w1];   // A0=(r0,r1)@d0, A1=(r0,r1)@d0+1
        __half2 B0 = sB[w0], B1 = sB[w1];   // rows 2,3
        float2 scf = *(const float2*)(scales + d0);
        __half2 sc = __floats2half2_rn(scf.x, scf.y);  // (scale d0, scale d0+1)
        // Row-major pairs, scaled in f16 like the reference, upcast exactly to f32.
        __half2 o0 = __hmul2(__halves2half2(__low2half(A0),  __low2half(A1)),  sc); // row0
        __half2 o1 = __hmul2(__halves2half2(__high2half(A0), __high2half(A1)), sc); // row1
        __half2 o2 = __hmul2(__halves2half2(__low2half(B0),  __low2half(B1)),  sc); // row2
        __half2 o3 = __hmul2(__halves2half2(__high2half(B0), __high2half(B1)), sc); // row3
        *(float2*)(out + base + d0) =
            make_float2(__half2float(__low2half(o0)), __half2float(__high2half(o0)));
        *(float2*)(out + base + DIMV + d0) =
            make_float2(__half2float(__low2half(o1)), __half2float(__high2half(o1)));
        *(float2*)(out + base + 2 * DIMV + d0) =
            make_float2(__half2float(__low2half(o2)), __half2float(__high2half(o2)));
        *(float2*)(out + base + 3 * DIMV + d0) =
            make_float2(__half2float(__low2half(o3)), __half2float(__high2half(o3)));
    }
}

extern "C" void kernel_launch(void* const* d_in, const int* in_sizes, int n_in,
                              void* d_out, int out_size) {
    const float* x      = (const float*)d_in[0];
    const int*   pairs  = (const int*)d_in[1];
    const float* theta  = (const float*)d_in[2];
    const float* scales = (const float*)d_in[3];
    (void)n_in;

    int N = in_sizes[0] / DIMV;   // 16384

    prep_kernel<<<(KROT * NPAIR + 255) / 256, 256>>>(theta, pairs);
    rot_kernel<<<N / ROWS, 256>>>(x, scales, (float*)d_out);
    (void)out_size;
}